// round 11
// baseline (speedup 1.0000x reference)
#include <cuda_runtime.h>
#include <cuda_fp16.h>
#include <cstdint>

#define PI_F 3.14159265358979323846f
#define WSCALE 1024.0f

constexpr int NROWS = 8192, DD = 64, BAS = 2048;
constexpr int MROWS   = 128;                 // rows per CTA (8 warps x 16)
constexpr int NB      = 64;                  // basis per iteration
constexpr int SPLITS  = 4;
constexpr int ITERS   = BAS / SPLITS / NB;   // 8
constexpr int THREADS = 256;

// smem byte offsets
constexpr int OFF_S1  = 0;        // 64 x 80 s8 (hi limb of S*2^13)
constexpr int OFF_S0  = 5120;     // 64 x 80 s8 (lo limb of S*2^13)
constexpr int OFF_S0N = 10240;    // 64 x 80 s8 (residual limb: S0' = (sv - S/2^13)*2^21)
constexpr int OFF_W   = 15360;    // 64 x 136 fp16 (k 0..63 sin, 64..127 cos) = 17408
constexpr int OFF_XS  = 0;        // overlay scratch: 128 x 68 f32 = 34816 (dead after prolog)
constexpr int SMEM_BYTES = 36864;

__device__ int8_t g_S1[BAS * DD], g_S0[BAS * DD], g_S0n[BAS * DD];  // [b][d]
__device__ __half g_Wsh[DD * BAS];                    // [c][b] sin coeff (-mat*w_s*1024)
__device__ __half g_Wch[DD * BAS];                    // [c][b] cos coeff ( mat*w_c*1024)
__device__ float g_part[SPLITS * NROWS * DD];

__device__ __forceinline__ uint32_t h2(float v0, float v1) {
  __half2 h = __floats2half2_rn(v0, v1);
  return *reinterpret_cast<uint32_t*>(&h);
}
__device__ __forceinline__ void mma16816(float* d, const uint32_t* a, uint32_t b0, uint32_t b1) {
  asm volatile(
      "mma.sync.aligned.m16n8k16.row.col.f32.f16.f16.f32 "
      "{%0,%1,%2,%3}, {%4,%5,%6,%7}, {%8,%9}, {%0,%1,%2,%3};"
      : "+f"(d[0]), "+f"(d[1]), "+f"(d[2]), "+f"(d[3])
      : "r"(a[0]), "r"(a[1]), "r"(a[2]), "r"(a[3]), "r"(b0), "r"(b1));
}
__device__ __forceinline__ void imma16832(int* d, const uint32_t* a, uint32_t b0, uint32_t b1) {
  asm volatile(
      "mma.sync.aligned.m16n8k32.row.col.s32.s8.s8.s32 "
      "{%0,%1,%2,%3}, {%4,%5,%6,%7}, {%8,%9}, {%0,%1,%2,%3};"
      : "+r"(d[0]), "+r"(d[1]), "+r"(d[2]), "+r"(d[3])
      : "r"(a[0]), "r"(a[1]), "r"(a[2]), "r"(a[3]), "r"(b0), "r"(b1));
}
// split fixed-point value into signed bytes: v = hi*256 + lo, lo,hi in [-128,127]
__device__ __forceinline__ void limbs(int v, int& hi, int& lo) {
  lo = ((v + 128) & 255) - 128;
  hi = (v - lo) >> 8;
}

// ---- precompute: one block per 8-basis stripe (grid 256), transposed W via smem ----
__global__ __launch_bounds__(256)
void precompute_kernel(const float* __restrict__ eps,
                       const float* __restrict__ lam,
                       const float* __restrict__ eta,
                       const float* __restrict__ w) {
  __shared__ float Ws[8][67], Wc[8][67];
  const int b0  = blockIdx.x * 8;
  const int tid = threadIdx.x;
  const float et2 = eta[0] * eta[0];

  #pragma unroll
  for (int i = 0; i < 2; i++) {
    int j = tid + i * 256;          // 0..511
    int b = j >> 6, d = j & 63;
    int idx = (b0 + b) * DD + d;
    float e = eps[idx], la = lam[d];
    float sv = e / (PI_F * la);     // angle = pi * (x . col),  |sv| < 3
    int S = __float2int_rn(sv * 8192.0f);                 // fits s16
    float r = fmaf((float)S, -1.220703125e-4f, sv);       // exact residual
    int s1, s0; limbs(S, s1, s0);
    g_S1[idx]  = (int8_t)s1;
    g_S0[idx]  = (int8_t)s0;
    g_S0n[idx] = (int8_t)__float2int_rn(r * 2097152.0f);  // r*2^21 in [-128,128)
    float m;
    if (d < 32) {
      m = eps[(b0 + b) * DD + d + 32] / lam[d + 32];
    } else {
      m = -eps[(b0 + b) * DD + d - 32] / lam[d - 32] - et2 * (e / la);
    }
    Ws[b][d] = -m * w[b0 + b] * WSCALE;        // -sin sign folded in
    Wc[b][d] =  m * w[BAS + b0 + b] * WSCALE;
  }
  __syncthreads();
  #pragma unroll
  for (int i = 0; i < 2; i++) {
    int j = tid + i * 256;          // 0..511
    int d = j >> 3, b = j & 7;
    size_t o = (size_t)d * BAS + b0 + b;
    g_Wsh[o] = __float2half_rn(Ws[b][d]);
    g_Wch[o] = __float2half_rn(Wc[b][d]);
  }
}

__global__ __launch_bounds__(THREADS, 2)
void ssgp_mma_kernel(const float* __restrict__ x) {
  extern __shared__ char sm[];
  const int tid  = threadIdx.x;
  const int wid  = tid >> 5;
  const int lane = tid & 31;
  const int gr   = lane >> 2;         // group row 0..7
  const int kl   = (lane & 3) * 2;    // fp16 k-pair base (GEMM2)
  const int kb4  = (lane & 3) * 4;    // s8 k-byte base (GEMM1)
  const int rb   = blockIdx.x >> 2;
  const int sp   = blockIdx.x & 3;
  const int r0   = rb * MROWS;

  // ---- prolog: stage X fp32 (coalesced), extract persistent s8 limb A-frags ----
  {
    float* Xs = reinterpret_cast<float*>(sm + OFF_XS);   // [128][68]
    #pragma unroll
    for (int i = 0; i < 8; i++) {
      int id  = tid + i * THREADS;     // 0..2047 float4s
      int row = id >> 4;
      int c4  = (id & 15) * 4;
      *reinterpret_cast<float4*>(&Xs[row * 68 + c4]) =
          *reinterpret_cast<const float4*>(&x[(size_t)(r0 + row) * DD + c4]);
    }
  }
  __syncthreads();
  uint32_t XA1[2][4], XA0[2][4];   // [kt2][a-reg], s8-packed limbs of x*2^12
  {
    const float* Xs = reinterpret_cast<const float*>(sm + OFF_XS);
    #pragma unroll
    for (int kt2 = 0; kt2 < 2; kt2++)
      #pragma unroll
      for (int q = 0; q < 4; q++) {
        int row = wid * 16 + gr + (q & 1) * 8;
        int d   = kt2 * 32 + (q >> 1) * 16 + kb4;
        float4 v = *reinterpret_cast<const float4*>(&Xs[row * 68 + d]);
        float vf[4] = {v.x, v.y, v.z, v.w};
        uint32_t p1 = 0, p0 = 0;
        #pragma unroll
        for (int bN = 0; bN < 4; bN++) {
          int xf = __float2int_rn(fminf(fmaxf(vf[bN] * 4096.0f, -32639.0f), 32639.0f));
          int h, l; limbs(xf, h, l);
          p1 |= (uint32_t)(h & 255) << (8 * bN);
          p0 |= (uint32_t)(l & 255) << (8 * bN);
        }
        XA1[kt2][q] = p1;
        XA0[kt2][q] = p0;
      }
  }
  __syncthreads();

  float f[8][4] = {};   // persistent output accum: 8 n-tiles x 4 regs

  #pragma unroll 1
  for (int it = 0; it < ITERS; it++) {
    const int b0 = sp * (BAS / SPLITS) + it * NB;

    // ---- stage S limb tiles: 3 x (64 rows x 64 s8), row pad 80 ----
    #pragma unroll
    for (int i = 0; i < 3; i++) {
      int id   = tid + i * THREADS;    // 0..767 granules (16B)
      int limb = id >> 8;              // 0:S1  1:S0  2:S0n
      int rem  = id & 255;
      int row  = rem >> 2;
      int c16  = rem & 3;
      const int8_t* src = (limb == 0 ? g_S1 : (limb == 1 ? g_S0 : g_S0n)) +
                          (size_t)(b0 + row) * DD + c16 * 16;
      char* dst = sm + limb * 5120 + row * 80 + c16 * 16;
      *reinterpret_cast<uint4*>(dst) = *reinterpret_cast<const uint4*>(src);
    }
    // ---- stage W tile: 64 x 128 fp16, row pad 136; k 0..63 sin, 64..127 cos ----
    #pragma unroll
    for (int i = 0; i < 4; i++) {
      int id   = tid + i * THREADS;    // 0..1023 granules
      int row  = id >> 4;
      int part = (id >> 3) & 1;
      int c8   = id & 7;
      const __half* src = (part ? g_Wch : g_Wsh) + (size_t)row * BAS + b0 + c8 * 8;
      char* dst = sm + OFF_W + (row * 136 + part * 64 + c8 * 8) * 2;
      *reinterpret_cast<uint4*>(dst) = *reinterpret_cast<const uint4*>(src);
    }
    __syncthreads();

    // ---- 4 basis-pairs: GEMM1 (exact s8, j-at-a-time to cap live regs) -> GEMM2 ----
    #pragma unroll
    for (int p = 0; p < 4; p++) {
      uint32_t Ash[4], Ach[4];
      const float ASC = PI_F / 33554432.0f;   // pi * 2^-25

      #pragma unroll
      for (int j = 0; j < 2; j++) {
        // Dh = X1*S1; Dm = X1*S0 + X0*S1; Dln = X0*S0 + X1*S0'   (12 live regs)
        int Dh[4] = {}, Dm[4] = {}, Dln[4] = {};
        #pragma unroll
        for (int kt2 = 0; kt2 < 2; kt2++) {
          int e = ((2 * p + j) * 8 + gr) * 80 + kt2 * 32 + kb4;
          uint32_t s1a = *reinterpret_cast<const uint32_t*>(sm + OFF_S1 + e);
          uint32_t s1b = *reinterpret_cast<const uint32_t*>(sm + OFF_S1 + e + 16);
          uint32_t s0a = *reinterpret_cast<const uint32_t*>(sm + OFF_S0 + e);
          uint32_t s0b = *reinterpret_cast<const uint32_t*>(sm + OFF_S0 + e + 16);
          uint32_t sna = *reinterpret_cast<const uint32_t*>(sm + OFF_S0N + e);
          uint32_t snb = *reinterpret_cast<const uint32_t*>(sm + OFF_S0N + e + 16);
          imma16832(Dh,  XA1[kt2], s1a, s1b);
          imma16832(Dm,  XA1[kt2], s0a, s0b);
          imma16832(Dm,  XA0[kt2], s1a, s1b);
          imma16832(Dln, XA0[kt2], s0a, s0b);
          imma16832(Dln, XA1[kt2], sna, snb);
        }
        // exact mod-2 reduction + sincos; pack fp16 A-frags (D-frag == A-frag layout)
        #pragma unroll
        for (int h = 0; h < 2; h++) {
          uint32_t t0 = ((uint32_t)Dh[2 * h] << 16) + ((uint32_t)Dm[2 * h] << 8) +
                        (uint32_t)Dln[2 * h];
          uint32_t t1 = ((uint32_t)Dh[2 * h + 1] << 16) + ((uint32_t)Dm[2 * h + 1] << 8) +
                        (uint32_t)Dln[2 * h + 1];
          int r0i = ((int)(t0 << 6)) >> 6;    // sign-extended 26-bit = angle*2^25 mod 2^26
          int r1i = ((int)(t1 << 6)) >> 6;
          float s0, c0, s1, c1;
          __sincosf((float)r0i * ASC, &s0, &c0);
          __sincosf((float)r1i * ASC, &s1, &c1);
          Ash[2 * j + h] = h2(s0, s1);
          Ach[2 * j + h] = h2(c0, c1);
        }
      }

      // GEMM2: f[nt] += P_sin . Wsin^T + P_cos . Wcos^T
      #pragma unroll
      for (int nt = 0; nt < 8; nt++) {
        int ebase = (nt * 8 + gr) * 136 + kl;
        const char* ws = sm + OFF_W + (ebase + 16 * p) * 2;        // sin k-tile
        const char* wc = sm + OFF_W + (ebase + 64 + 16 * p) * 2;   // cos k-tile
        uint32_t s0 = *reinterpret_cast<const uint32_t*>(ws);
        uint32_t s1 = *reinterpret_cast<const uint32_t*>(ws + 16);
        uint32_t c0 = *reinterpret_cast<const uint32_t*>(wc);
        uint32_t c1 = *reinterpret_cast<const uint32_t*>(wc + 16);
        mma16816(f[nt], Ash, s0, s1);
        mma16816(f[nt], Ach, c0, c1);
      }
    }
    __syncthreads();   // before restaging next tile
  }

  // ---- epilogue: write partials ----
  {
    float* po = g_part + (size_t)sp * NROWS * DD;
    int row = r0 + wid * 16 + gr;
    #pragma unroll
    for (int nt = 0; nt < 8; nt++) {
      int col = nt * 8 + kl;
      *reinterpret_cast<float2*>(&po[(size_t)row * DD + col]) =
          make_float2(f[nt][0], f[nt][1]);
      *reinterpret_cast<float2*>(&po[(size_t)(row + 8) * DD + col]) =
          make_float2(f[nt][2], f[nt][3]);
    }
  }
}

__global__ void reduce_kernel(float* __restrict__ out) {
  int i = blockIdx.x * blockDim.x + threadIdx.x;
  constexpr int N4 = NROWS * DD / 4;
  if (i >= N4) return;
  const float4* p = reinterpret_cast<const float4*>(g_part);
  float4 a = p[i];
  #pragma unroll
  for (int s = 1; s < SPLITS; s++) {
    float4 b = p[(size_t)s * N4 + i];
    a.x += b.x; a.y += b.y; a.z += b.z; a.w += b.w;
  }
  const float inv = 1.0f / WSCALE;
  a.x *= inv; a.y *= inv; a.z *= inv; a.w *= inv;
  reinterpret_cast<float4*>(out)[i] = a;
}

extern "C" void kernel_launch(void* const* d_in, const int* in_sizes, int n_in,
                              void* d_out, int out_size) {
  // inputs (metadata order): t, x, epsilon, lam, eta, w
  const float* x_in = (const float*)d_in[1];
  const float* eps  = (const float*)d_in[2];
  const float* lam  = (const float*)d_in[3];
  const float* eta  = (const float*)d_in[4];
  const float* w    = (const float*)d_in[5];
  float* out = (float*)d_out;

  cudaFuncSetAttribute(ssgp_mma_kernel,
                       cudaFuncAttributeMaxDynamicSharedMemorySize, SMEM_BYTES);

  precompute_kernel<<<BAS / 8, 256>>>(eps, lam, eta, w);
  ssgp_mma_kernel<<<(NROWS / MROWS) * SPLITS, THREADS, SMEM_BYTES>>>(x_in);
  reduce_kernel<<<(NROWS * DD / 4 + 255) / 256, 256>>>(out);
}

// round 13
// speedup vs baseline: 2.5370x; 2.5370x over previous
#include <cuda_runtime.h>
#include <cuda_fp16.h>
#include <cstdint>

#define PI_F 3.14159265358979323846f
#define WSCALE 1024.0f

constexpr int NROWS = 8192, DD = 64, BAS = 2048;
constexpr int MROWS   = 128;                 // rows per CTA (8 warps x 16)
constexpr int NB      = 64;                  // basis per iteration
constexpr int SPLITS  = 4;
constexpr int ITERS   = BAS / SPLITS / NB;   // 8
constexpr int THREADS = 256;

// per-buffer smem byte offsets (double-buffered)
constexpr int OFF_SHI = 0;        // 64 x 72 fp16 = 9216
constexpr int OFF_SLO = 9216;     // 64 x 72 fp16
constexpr int OFF_W   = 18432;    // 64 x 136 fp16 (k 0..63 sin, 64..127 cos) = 17408
constexpr int BUF     = 36864;
constexpr int SMEM_BYTES = 2 * BUF;          // 73728; X scratch (34816) overlays at prolog

__device__ __half g_Shi[BAS * DD], g_Slo[BAS * DD];   // [b][d]
__device__ __half g_Wsh[DD * BAS];                    // [c][b]  sin coeff (-mat*w_s*1024)
__device__ __half g_Wch[DD * BAS];                    // [c][b]  cos coeff ( mat*w_c*1024)
__device__ float g_part[SPLITS * NROWS * DD];

__device__ __forceinline__ uint32_t h2(float v0, float v1) {
  __half2 h = __floats2half2_rn(v0, v1);
  return *reinterpret_cast<uint32_t*>(&h);
}
__device__ __forceinline__ void split2h(float v0, float v1, uint32_t& hi, uint32_t& lo) {
  hi = h2(v0, v1);
  float2 hf = __half22float2(*reinterpret_cast<__half2*>(&hi));
  lo = h2(v0 - hf.x, v1 - hf.y);
}
__device__ __forceinline__ void mma16816(float* d, const uint32_t* a, uint32_t b0, uint32_t b1) {
  asm volatile(
      "mma.sync.aligned.m16n8k16.row.col.f32.f16.f16.f32 "
      "{%0,%1,%2,%3}, {%4,%5,%6,%7}, {%8,%9}, {%0,%1,%2,%3};"
      : "+f"(d[0]), "+f"(d[1]), "+f"(d[2]), "+f"(d[3])
      : "r"(a[0]), "r"(a[1]), "r"(a[2]), "r"(a[3]), "r"(b0), "r"(b1));
}
__device__ __forceinline__ void cpasync16(uint32_t dst, const void* src) {
  asm volatile("cp.async.cg.shared.global [%0], [%1], 16;" :: "r"(dst), "l"(src));
}

// ---- precompute: one block per 8-basis stripe (grid 256), transposed W via smem ----
__global__ __launch_bounds__(256)
void precompute_kernel(const float* __restrict__ eps,
                       const float* __restrict__ lam,
                       const float* __restrict__ eta,
                       const float* __restrict__ w) {
  __shared__ float Ws[8][67], Wc[8][67];
  const int b0  = blockIdx.x * 8;
  const int tid = threadIdx.x;
  const float et2 = eta[0] * eta[0];

  #pragma unroll
  for (int i = 0; i < 2; i++) {
    int j = tid + i * 256;          // 0..511
    int b = j >> 6, d = j & 63;
    int idx = (b0 + b) * DD + d;
    float e = eps[idx], la = lam[d];
    float sv = e / (PI_F * la);     // angle = pi * (x . col)
    __half h = __float2half_rn(sv);
    g_Shi[idx] = h;
    g_Slo[idx] = __float2half_rn(sv - __half2float(h));
    float m;
    if (d < 32) {
      m = eps[(b0 + b) * DD + d + 32] / lam[d + 32];
    } else {
      m = -eps[(b0 + b) * DD + d - 32] / lam[d - 32] - et2 * (e / la);
    }
    Ws[b][d] = -m * w[b0 + b] * WSCALE;        // -sin sign folded in
    Wc[b][d] =  m * w[BAS + b0 + b] * WSCALE;
  }
  __syncthreads();
  #pragma unroll
  for (int i = 0; i < 2; i++) {
    int j = tid + i * 256;          // 0..511
    int d = j >> 3, b = j & 7;
    size_t o = (size_t)d * BAS + b0 + b;
    g_Wsh[o] = __float2half_rn(Ws[b][d]);
    g_Wch[o] = __float2half_rn(Wc[b][d]);
  }
}

__global__ __launch_bounds__(THREADS, 2)
void ssgp_mma_kernel(const float* __restrict__ x) {
  extern __shared__ char sm[];
  const uint32_t smb = (uint32_t)__cvta_generic_to_shared(sm);
  const int tid  = threadIdx.x;
  const int wid  = tid >> 5;
  const int lane = tid & 31;
  const int gr   = lane >> 2;         // group row 0..7
  const int kl   = (lane & 3) * 2;    // fp16 k-pair base
  const int rb   = blockIdx.x >> 2;
  const int sp   = blockIdx.x & 3;
  const int r0   = rb * MROWS;

  // ---- prolog: stage X fp32 into scratch (overlay), extract persistent A-frags ----
  {
    float* Xs = reinterpret_cast<float*>(sm);   // [128][68]
    #pragma unroll
    for (int i = 0; i < 8; i++) {
      int id  = tid + i * THREADS;     // 0..2047 float4s
      int row = id >> 4;
      int c4  = (id & 15) * 4;
      *reinterpret_cast<float4*>(&Xs[row * 68 + c4]) =
          *reinterpret_cast<const float4*>(&x[(size_t)(r0 + row) * DD + c4]);
    }
  }
  __syncthreads();
  uint32_t Xhi[4][4], Xlo[4][4];
  {
    const float* Xs = reinterpret_cast<const float*>(sm);
    #pragma unroll
    for (int kt = 0; kt < 4; kt++)
      #pragma unroll
      for (int q = 0; q < 4; q++) {
        int rr = wid * 16 + gr + (q & 1) * 8;
        int kk = kt * 16 + kl + (q >> 1) * 8;
        float2 v = *reinterpret_cast<const float2*>(&Xs[rr * 68 + kk]);
        split2h(v.x, v.y, Xhi[kt][q], Xlo[kt][q]);
      }
  }
  __syncthreads();

  // ---- async tile staging (double-buffered) ----
  auto stage_tile = [&](int it) {
    const int b0 = sp * (BAS / SPLITS) + it * NB;
    const uint32_t ba = smb + (it & 1) * BUF;
    #pragma unroll
    for (int i = 0; i < 4; i++) {            // S hi/lo: 1024 granules
      int id   = tid + i * THREADS;
      int tile = id >> 9;
      int rem  = id & 511;
      int row  = rem >> 3;
      int c8   = rem & 7;
      const __half* src = (tile ? g_Slo : g_Shi) + (size_t)(b0 + row) * DD + c8 * 8;
      cpasync16(ba + (tile ? OFF_SLO : OFF_SHI) + (row * 72 + c8 * 8) * 2, src);
    }
    #pragma unroll
    for (int i = 0; i < 4; i++) {            // W: 1024 granules
      int id   = tid + i * THREADS;
      int row  = id >> 4;
      int part = (id >> 3) & 1;
      int c8   = id & 7;
      const __half* src = (part ? g_Wch : g_Wsh) + (size_t)row * BAS + b0 + c8 * 8;
      cpasync16(ba + OFF_W + (row * 136 + part * 64 + c8 * 8) * 2, src);
    }
    asm volatile("cp.async.commit_group;" ::: "memory");
  };

  float f[8][4] = {};   // persistent output accum: 8 n-tiles x 4 regs

  stage_tile(0);

  #pragma unroll 1
  for (int it = 0; it < ITERS; it++) {
    if (it + 1 < ITERS) {
      stage_tile(it + 1);
      asm volatile("cp.async.wait_group 1;" ::: "memory");
    } else {
      asm volatile("cp.async.wait_group 0;" ::: "memory");
    }
    __syncthreads();
    const char* buf = sm + (it & 1) * BUF;

    // ---- 4 basis-pairs: GEMM1 (reg angles) -> sincos -> GEMM2 accumulate ----
    #pragma unroll
    for (int p = 0; p < 4; p++) {
      // GEMM1 split accumulators: Da = hi*hi (4-chain), Db = cross terms (8-chain)
      float Da[2][4] = {}, Db[2][4] = {};
      #pragma unroll
      for (int kt = 0; kt < 4; kt++) {
        #pragma unroll
        for (int j = 0; j < 2; j++) {
          int e = ((2 * p + j) * 8 + gr) * 72 + kt * 16 + kl;
          const char* sh = buf + OFF_SHI + e * 2;
          const char* sl = buf + OFF_SLO + e * 2;
          uint32_t bh0 = *reinterpret_cast<const uint32_t*>(sh);
          uint32_t bh1 = *reinterpret_cast<const uint32_t*>(sh + 16);
          uint32_t bl0 = *reinterpret_cast<const uint32_t*>(sl);
          uint32_t bl1 = *reinterpret_cast<const uint32_t*>(sl + 16);
          mma16816(Da[j], Xhi[kt], bh0, bh1);
          mma16816(Db[j], Xhi[kt], bl0, bl1);
          mma16816(Db[j], Xlo[kt], bh0, bh1);
        }
      }

      // sincos; pack hi-only fp16 A-frags for GEMM2 (D-frag == A-frag layout)
      uint32_t Ash[4], Ach[4];
      #pragma unroll
      for (int j = 0; j < 2; j++)
        #pragma unroll
        for (int h = 0; h < 2; h++) {
          float v0 = Da[j][2 * h]     + Db[j][2 * h];
          float v1 = Da[j][2 * h + 1] + Db[j][2 * h + 1];
          float a0 = fmaf(-2.0f, rintf(v0 * 0.5f), v0) * PI_F;
          float a1 = fmaf(-2.0f, rintf(v1 * 0.5f), v1) * PI_F;
          float s0, c0, s1, c1;
          __sincosf(a0, &s0, &c0);
          __sincosf(a1, &s1, &c1);
          int idx = 2 * j + h;
          Ash[idx] = h2(s0, s1);
          Ach[idx] = h2(c0, c1);
        }

      // GEMM2: f[nt] += P_sin . Wsin^T + P_cos . Wcos^T  (hi-only W)
      #pragma unroll
      for (int nt = 0; nt < 8; nt++) {
        int ebase = (nt * 8 + gr) * 136 + kl;
        const char* ws = buf + OFF_W + (ebase + 16 * p) * 2;        // sin k-tile
        const char* wc = buf + OFF_W + (ebase + 64 + 16 * p) * 2;   // cos k-tile
        uint32_t s0 = *reinterpret_cast<const uint32_t*>(ws);
        uint32_t s1 = *reinterpret_cast<const uint32_t*>(ws + 16);
        uint32_t c0 = *reinterpret_cast<const uint32_t*>(wc);
        uint32_t c1 = *reinterpret_cast<const uint32_t*>(wc + 16);
        mma16816(f[nt], Ash, s0, s1);
        mma16816(f[nt], Ach, c0, c1);
      }
    }
    __syncthreads();   // compute done before this buffer is re-staged at it+2
  }

  // ---- epilogue: write partials ----
  {
    float* po = g_part + (size_t)sp * NROWS * DD;
    int row = r0 + wid * 16 + gr;
    #pragma unroll
    for (int nt = 0; nt < 8; nt++) {
      int col = nt * 8 + kl;
      *reinterpret_cast<float2*>(&po[(size_t)row * DD + col]) =
          make_float2(f[nt][0], f[nt][1]);
      *reinterpret_cast<float2*>(&po[(size_t)(row + 8) * DD + col]) =
          make_float2(f[nt][2], f[nt][3]);
    }
  }
}

__global__ void reduce_kernel(float* __restrict__ out) {
  int i = blockIdx.x * blockDim.x + threadIdx.x;
  constexpr int N4 = NROWS * DD / 4;
  if (i >= N4) return;
  const float4* p = reinterpret_cast<const float4*>(g_part);
  float4 a = p[i];
  #pragma unroll
  for (int s = 1; s < SPLITS; s++) {
    float4 b = p[(size_t)s * N4 + i];
    a.x += b.x; a.y += b.y; a.z += b.z; a.w += b.w;
  }
  const float inv = 1.0f / WSCALE;
  a.x *= inv; a.y *= inv; a.z *= inv; a.w *= inv;
  reinterpret_cast<float4*>(out)[i] = a;
}

extern "C" void kernel_launch(void* const* d_in, const int* in_sizes, int n_in,
                              void* d_out, int out_size) {
  // inputs (metadata order): t, x, epsilon, lam, eta, w
  const float* x_in = (const float*)d_in[1];
  const float* eps  = (const float*)d_in[2];
  const float* lam  = (const float*)d_in[3];
  const float* eta  = (const float*)d_in[4];
  const float* w    = (const float*)d_in[5];
  float* out = (float*)d_out;

  cudaFuncSetAttribute(ssgp_mma_kernel,
                       cudaFuncAttributeMaxDynamicSharedMemorySize, SMEM_BYTES);

  precompute_kernel<<<BAS / 8, 256>>>(eps, lam, eta, w);
  ssgp_mma_kernel<<<(NROWS / MROWS) * SPLITS, THREADS, SMEM_BYTES>>>(x_in);
  reduce_kernel<<<(NROWS * DD / 4 + 255) / 256, 256>>>(out);
}

// round 14
// speedup vs baseline: 2.6471x; 1.0434x over previous
#include <cuda_runtime.h>
#include <cuda_fp16.h>
#include <cstdint>

#define PI_F 3.14159265358979323846f
#define WSCALE 1024.0f

constexpr int NROWS = 8192, DD = 64, BAS = 2048;
constexpr int MROWS   = 128;                 // rows per CTA (8 warps x 16)
constexpr int NB      = 64;                  // basis per iteration
constexpr int SPLITS  = 4;
constexpr int ITERS   = BAS / SPLITS / NB;   // 8
constexpr int THREADS = 256;

// per-buffer smem byte offsets (double-buffered)
constexpr int OFF_SHI = 0;        // 64 x 72 fp16 = 9216
constexpr int OFF_SLO = 9216;     // 64 x 72 fp16
constexpr int OFF_W   = 18432;    // 64 x 136 fp16 (k 0..63 sin, 64..127 cos) = 17408
constexpr int BUF     = 36864;
constexpr int SMEM_BYTES = 2 * BUF;          // 73728; X scratch (34816) overlays at prolog

__device__ __half g_Shi[BAS * DD], g_Slo[BAS * DD];   // [b][d]
__device__ __half g_Wsh[DD * BAS];                    // [c][b]  sin coeff (-mat*w_s*1024)
__device__ __half g_Wch[DD * BAS];                    // [c][b]  cos coeff ( mat*w_c*1024)
__device__ float g_part[SPLITS * NROWS * DD];

__device__ __forceinline__ uint32_t h2(float v0, float v1) {
  __half2 h = __floats2half2_rn(v0, v1);
  return *reinterpret_cast<uint32_t*>(&h);
}
__device__ __forceinline__ void split2h(float v0, float v1, uint32_t& hi, uint32_t& lo) {
  hi = h2(v0, v1);
  float2 hf = __half22float2(*reinterpret_cast<__half2*>(&hi));
  lo = h2(v0 - hf.x, v1 - hf.y);
}
__device__ __forceinline__ void mma16816(float* d, const uint32_t* a, uint32_t b0, uint32_t b1) {
  asm volatile(
      "mma.sync.aligned.m16n8k16.row.col.f32.f16.f16.f32 "
      "{%0,%1,%2,%3}, {%4,%5,%6,%7}, {%8,%9}, {%0,%1,%2,%3};"
      : "+f"(d[0]), "+f"(d[1]), "+f"(d[2]), "+f"(d[3])
      : "r"(a[0]), "r"(a[1]), "r"(a[2]), "r"(a[3]), "r"(b0), "r"(b1));
}
__device__ __forceinline__ void ldsm4(uint32_t* r, uint32_t addr) {
  asm volatile("ldmatrix.sync.aligned.m8n8.x4.shared.b16 {%0,%1,%2,%3}, [%4];"
               : "=r"(r[0]), "=r"(r[1]), "=r"(r[2]), "=r"(r[3]) : "r"(addr));
}
__device__ __forceinline__ void cpasync16(uint32_t dst, const void* src) {
  asm volatile("cp.async.cg.shared.global [%0], [%1], 16;" :: "r"(dst), "l"(src));
}

// ---- precompute: one block per 4-basis stripe (grid 512), transposed W via smem ----
__global__ __launch_bounds__(256)
void precompute_kernel(const float* __restrict__ eps,
                       const float* __restrict__ lam,
                       const float* __restrict__ eta,
                       const float* __restrict__ w) {
  __shared__ float Ws[4][67], Wc[4][67];
  const int b0  = blockIdx.x * 4;
  const int tid = threadIdx.x;
  const float et2 = eta[0] * eta[0];

  {
    int b = tid >> 6, d = tid & 63;
    int idx = (b0 + b) * DD + d;
    float e = eps[idx], la = lam[d];
    float sv = e / (PI_F * la);     // angle = pi * (x . col)
    __half h = __float2half_rn(sv);
    g_Shi[idx] = h;
    g_Slo[idx] = __float2half_rn(sv - __half2float(h));
    float m;
    if (d < 32) {
      m = eps[(b0 + b) * DD + d + 32] / lam[d + 32];
    } else {
      m = -eps[(b0 + b) * DD + d - 32] / lam[d - 32] - et2 * (e / la);
    }
    Ws[b][d] = -m * w[b0 + b] * WSCALE;        // -sin sign folded in
    Wc[b][d] =  m * w[BAS + b0 + b] * WSCALE;
  }
  __syncthreads();
  {
    int d = tid >> 2, b = tid & 3;
    size_t o = (size_t)d * BAS + b0 + b;
    g_Wsh[o] = __float2half_rn(Ws[b][d]);
    g_Wch[o] = __float2half_rn(Wc[b][d]);
  }
}

__global__ __launch_bounds__(THREADS, 2)
void ssgp_mma_kernel(const float* __restrict__ x) {
  extern __shared__ char sm[];
  const uint32_t smb = (uint32_t)__cvta_generic_to_shared(sm);
  const int tid  = threadIdx.x;
  const int wid  = tid >> 5;
  const int lane = tid & 31;
  const int gr   = lane >> 2;         // group row 0..7
  const int kl   = (lane & 3) * 2;    // fp16 k-pair base
  const int rb   = blockIdx.x >> 2;
  const int sp   = blockIdx.x & 3;
  const int r0   = rb * MROWS;

  // ldmatrix lane base offsets (bytes)
  const uint32_t loffS = (uint32_t)(((lane & 7) * 72 + (lane >> 3) * 8) * 2);
  const uint32_t loffW = (uint32_t)(((lane & 7) * 136 + ((lane >> 4) & 1) * 64 +
                                     ((lane >> 3) & 1) * 8) * 2);

  // ---- prolog: stage X fp32 into scratch (overlay), extract persistent A-frags ----
  {
    float* Xs = reinterpret_cast<float*>(sm);   // [128][68]
    #pragma unroll
    for (int i = 0; i < 8; i++) {
      int id  = tid + i * THREADS;     // 0..2047 float4s
      int row = id >> 4;
      int c4  = (id & 15) * 4;
      *reinterpret_cast<float4*>(&Xs[row * 68 + c4]) =
          *reinterpret_cast<const float4*>(&x[(size_t)(r0 + row) * DD + c4]);
    }
  }
  __syncthreads();
  uint32_t Xhi[4][4], Xlo[4][4];
  {
    const float* Xs = reinterpret_cast<const float*>(sm);
    #pragma unroll
    for (int kt = 0; kt < 4; kt++)
      #pragma unroll
      for (int q = 0; q < 4; q++) {
        int rr = wid * 16 + gr + (q & 1) * 8;
        int kk = kt * 16 + kl + (q >> 1) * 8;
        float2 v = *reinterpret_cast<const float2*>(&Xs[rr * 68 + kk]);
        split2h(v.x, v.y, Xhi[kt][q], Xlo[kt][q]);
      }
  }
  __syncthreads();

  // ---- async tile staging (double-buffered) ----
  auto stage_tile = [&](int it) {
    const int b0 = sp * (BAS / SPLITS) + it * NB;
    const uint32_t ba = smb + (it & 1) * BUF;
    #pragma unroll
    for (int i = 0; i < 4; i++) {            // S hi/lo: 1024 granules
      int id   = tid + i * THREADS;
      int tile = id >> 9;
      int rem  = id & 511;
      int row  = rem >> 3;
      int c8   = rem & 7;
      const __half* src = (tile ? g_Slo : g_Shi) + (size_t)(b0 + row) * DD + c8 * 8;
      cpasync16(ba + (tile ? OFF_SLO : OFF_SHI) + (row * 72 + c8 * 8) * 2, src);
    }
    #pragma unroll
    for (int i = 0; i < 4; i++) {            // W: 1024 granules
      int id   = tid + i * THREADS;
      int row  = id >> 4;
      int part = (id >> 3) & 1;
      int c8   = id & 7;
      const __half* src = (part ? g_Wch : g_Wsh) + (size_t)row * BAS + b0 + c8 * 8;
      cpasync16(ba + OFF_W + (row * 136 + part * 64 + c8 * 8) * 2, src);
    }
    asm volatile("cp.async.commit_group;" ::: "memory");
  };

  float f[8][4] = {};   // persistent output accum: 8 n-tiles x 4 regs

  stage_tile(0);

  #pragma unroll 1
  for (int it = 0; it < ITERS; it++) {
    if (it + 1 < ITERS) {
      stage_tile(it + 1);
      asm volatile("cp.async.wait_group 1;" ::: "memory");
    } else {
      asm volatile("cp.async.wait_group 0;" ::: "memory");
    }
    __syncthreads();
    const uint32_t ba = smb + (it & 1) * BUF;
    const uint32_t sShi = ba + OFF_SHI + loffS;
    const uint32_t sSlo = ba + OFF_SLO + loffS;
    const uint32_t sW   = ba + OFF_W + loffW;

    // ---- 4 basis-pairs: GEMM1 (reg angles) -> sincos -> GEMM2 accumulate ----
    #pragma unroll
    for (int p = 0; p < 4; p++) {
      // GEMM1 split accumulators: Da = hi*hi, Db = cross terms
      float Da[2][4] = {}, Db[2][4] = {};
      #pragma unroll
      for (int j = 0; j < 2; j++) {
        #pragma unroll
        for (int kp = 0; kp < 2; kp++) {     // kt pair {2kp, 2kp+1}
          uint32_t rowoff = (uint32_t)((((2 * p + j) * 8) * 72 + kp * 32) * 2);
          uint32_t sh[4], sl[4];
          ldsm4(sh, sShi + rowoff);
          ldsm4(sl, sSlo + rowoff);
          mma16816(Da[j], Xhi[2 * kp], sh[0], sh[1]);
          mma16816(Db[j], Xhi[2 * kp], sl[0], sl[1]);
          mma16816(Db[j], Xlo[2 * kp], sh[0], sh[1]);
          mma16816(Da[j], Xhi[2 * kp + 1], sh[2], sh[3]);
          mma16816(Db[j], Xhi[2 * kp + 1], sl[2], sl[3]);
          mma16816(Db[j], Xlo[2 * kp + 1], sh[2], sh[3]);
        }
      }

      // sincos; pack hi-only fp16 A-frags for GEMM2 (D-frag == A-frag layout)
      uint32_t Ash[4], Ach[4];
      #pragma unroll
      for (int j = 0; j < 2; j++)
        #pragma unroll
        for (int h = 0; h < 2; h++) {
          float v0 = Da[j][2 * h]     + Db[j][2 * h];
          float v1 = Da[j][2 * h + 1] + Db[j][2 * h + 1];
          float a0 = fmaf(-2.0f, rintf(v0 * 0.5f), v0) * PI_F;
          float a1 = fmaf(-2.0f, rintf(v1 * 0.5f), v1) * PI_F;
          float s0, c0, s1, c1;
          __sincosf(a0, &s0, &c0);
          __sincosf(a1, &s1, &c1);
          int idx = 2 * j + h;
          Ash[idx] = h2(s0, s1);
          Ach[idx] = h2(c0, c1);
        }

      // GEMM2: f[nt] += P_sin . Wsin^T + P_cos . Wcos^T (one ldmatrix per nt)
      #pragma unroll
      for (int nt = 0; nt < 8; nt++) {
        uint32_t wr[4];
        ldsm4(wr, sW + (uint32_t)((nt * 8 * 136 + 16 * p) * 2));
        mma16816(f[nt], Ash, wr[0], wr[1]);
        mma16816(f[nt], Ach, wr[2], wr[3]);
      }
    }
    __syncthreads();   // compute done before this buffer is re-staged at it+2
  }

  // ---- epilogue: write partials ----
  {
    float* po = g_part + (size_t)sp * NROWS * DD;
    int row = r0 + wid * 16 + gr;
    #pragma unroll
    for (int nt = 0; nt < 8; nt++) {
      int col = nt * 8 + kl;
      *reinterpret_cast<float2*>(&po[(size_t)row * DD + col]) =
          make_float2(f[nt][0], f[nt][1]);
      *reinterpret_cast<float2*>(&po[(size_t)(row + 8) * DD + col]) =
          make_float2(f[nt][2], f[nt][3]);
    }
  }
}

__global__ void reduce_kernel(float* __restrict__ out) {
  int i = blockIdx.x * blockDim.x + threadIdx.x;
  constexpr int N4 = NROWS * DD / 4;
  if (i >= N4) return;
  const float4* p = reinterpret_cast<const float4*>(g_part);
  float4 a = p[i];
  #pragma unroll
  for (int s = 1; s < SPLITS; s++) {
    float4 b = p[(size_t)s * N4 + i];
    a.x += b.x; a.y += b.y; a.z += b.z; a.w += b.w;
  }
  const float inv = 1.0f / WSCALE;
  a.x *= inv; a.y *= inv; a.z *= inv; a.w *= inv;
  reinterpret_cast<float4*>(out)[i] = a;
}

extern "C" void kernel_launch(void* const* d_in, const int* in_sizes, int n_in,
                              void* d_out, int out_size) {
  // inputs (metadata order): t, x, epsilon, lam, eta, w
  const float* x_in = (const float*)d_in[1];
  const float* eps  = (const float*)d_in[2];
  const float* lam  = (const float*)d_in[3];
  const float* eta  = (const float*)d_in[4];
  const float* w    = (const float*)d_in[5];
  float* out = (float*)d_out;

  cudaFuncSetAttribute(ssgp_mma_kernel,
                       cudaFuncAttributeMaxDynamicSharedMemorySize, SMEM_BYTES);

  precompute_kernel<<<BAS / 4, 256>>>(eps, lam, eta, w);
  ssgp_mma_kernel<<<(NROWS / MROWS) * SPLITS, THREADS, SMEM_BYTES>>>(x_in);
  reduce_kernel<<<(NROWS * DD / 4 + 255) / 256, 256>>>(out);
}